// round 3
// baseline (speedup 1.0000x reference)
#include <cuda_runtime.h>
#include <cuda_bf16.h>
#include <math.h>

// Problem constants
static constexpr int Bn  = 256;   // batch
static constexpr int Tn  = 256;   // time
static constexpr int NIN = 128;
static constexpr int Hh  = 256;   // hidden
static constexpr int G3  = 768;   // 3*H
static constexpr int Mrows = Bn * Tn; // 65536

// ---------------- scratch (device globals; no allocation allowed) ----------
__device__ float g_xg[(size_t)2 * Mrows * G3];   // [dir][m][768]  (~403 MB)
__device__ float g_rec1[(size_t)Mrows * 2 * Hh]; // [m][512]
__device__ float g_rec2[(size_t)Mrows * 2 * Hh]; // [m][512]
__device__ float g_merged[Bn * 2 * Hh];          // [b][512]

// ---------------- f32x2 packed-fp32 helpers (sm_103a) -----------------------
__device__ __forceinline__ unsigned long long pack2(float x, float y) {
    unsigned long long r;
    asm("mov.b64 %0, {%1, %2};" : "=l"(r) : "f"(x), "f"(y));
    return r;
}
__device__ __forceinline__ void unpack2(unsigned long long v, float& x, float& y) {
    asm("mov.b64 {%0, %1}, %2;" : "=f"(x), "=f"(y) : "l"(v));
}
__device__ __forceinline__ void ffma2(unsigned long long& d,
                                      unsigned long long a, unsigned long long b) {
    // d = a*b + d, lanewise on packed (lo,hi) fp32 pairs
    asm("fma.rn.f32x2 %0, %1, %2, %0;" : "+l"(d) : "l"(a), "l"(b));
}

// ============================================================================
// Input-gate GEMM:  xg[dir][m][g] = sum_k A[m][k] * W_dir[g][k] + bih_dir[g]
// A: [M][K] row-major (K = NIN for layer1, 512 for layer2)
// W: [768][K] row-major, both directions passed.
// Tiles: BM=BN=128, BK=16, 256 threads, 8x8 per thread, f32x2 accumulation,
// double-buffered SMEM with register prefetch.
// grid = (12 n-tiles [6 per dir], 512 m-tiles)
// ============================================================================
template <int K>
__global__ void __launch_bounds__(256, 2)
igemm_kernel(const float* __restrict__ A,
             const float* __restrict__ Wf, const float* __restrict__ Wr,
             const float* __restrict__ bf, const float* __restrict__ br,
             float* __restrict__ xg) {
    constexpr int KT = K / 16;
    const int nt  = blockIdx.x;
    const int dir = nt / 6;
    const int n0  = (nt % 6) * 128;
    const int m0  = blockIdx.y * 128;
    const float* W    = dir ? Wr : Wf;
    const float* bias = dir ? br : bf;
    float* xgout = xg + (size_t)dir * Mrows * G3;

    __shared__ __align__(16) float As[2][16][128];
    __shared__ __align__(16) float Ws[2][16][128];

    const int tid = threadIdx.x;
    const int tm  = (tid >> 4) << 3;  // 0..120
    const int tn  = (tid & 15) << 3;  // 0..120

    // loader slots: 512 float4 per tile, 2 per thread
    const int row0 = (tid) >> 2,        kq0 = (tid) & 3;
    const int row1 = (tid + 256) >> 2,  kq1 = (tid + 256) & 3;

    float4 ra0, ra1, rw0, rw1;
    auto ldg_tile = [&](int kt) {
        const float* ap = A + (size_t)(m0)*K + kt * 16;
        const float* wp = W + (size_t)(n0)*K + kt * 16;
        ra0 = *(const float4*)(ap + (size_t)row0 * K + kq0 * 4);
        ra1 = *(const float4*)(ap + (size_t)row1 * K + kq1 * 4);
        rw0 = *(const float4*)(wp + (size_t)row0 * K + kq0 * 4);
        rw1 = *(const float4*)(wp + (size_t)row1 * K + kq1 * 4);
    };
    auto sts_tile = [&](int s) {
        float a0v[4] = {ra0.x, ra0.y, ra0.z, ra0.w};
        float a1v[4] = {ra1.x, ra1.y, ra1.z, ra1.w};
        float w0v[4] = {rw0.x, rw0.y, rw0.z, rw0.w};
        float w1v[4] = {rw1.x, rw1.y, rw1.z, rw1.w};
#pragma unroll
        for (int j = 0; j < 4; j++) {
            As[s][kq0 * 4 + j][row0] = a0v[j];
            As[s][kq1 * 4 + j][row1] = a1v[j];
            Ws[s][kq0 * 4 + j][row0] = w0v[j];
            Ws[s][kq1 * 4 + j][row1] = w1v[j];
        }
    };

    unsigned long long acc[8][4];
#pragma unroll
    for (int m = 0; m < 8; m++)
#pragma unroll
        for (int p = 0; p < 4; p++) acc[m][p] = 0ull;

    ldg_tile(0);
    sts_tile(0);
    __syncthreads();

    int s = 0;
    for (int kt = 0; kt < KT; kt++) {
        if (kt + 1 < KT) ldg_tile(kt + 1);
#pragma unroll
        for (int k = 0; k < 16; k++) {
            float4 a0 = *(const float4*)&As[s][k][tm];
            float4 a1 = *(const float4*)&As[s][k][tm + 4];
            ulonglong2 b0 = *(const ulonglong2*)&Ws[s][k][tn];
            ulonglong2 b1 = *(const ulonglong2*)&Ws[s][k][tn + 4];
            float av[8] = {a0.x, a0.y, a0.z, a0.w, a1.x, a1.y, a1.z, a1.w};
#pragma unroll
            for (int m = 0; m < 8; m++) {
                unsigned long long ar = pack2(av[m], av[m]);
                ffma2(acc[m][0], ar, b0.x);
                ffma2(acc[m][1], ar, b0.y);
                ffma2(acc[m][2], ar, b1.x);
                ffma2(acc[m][3], ar, b1.y);
            }
        }
        if (kt + 1 < KT) {
            sts_tile(s ^ 1);
            __syncthreads();
            s ^= 1;
        }
    }

    float bias8[8];
#pragma unroll
    for (int j = 0; j < 8; j++) bias8[j] = bias[n0 + tn + j];

#pragma unroll
    for (int m = 0; m < 8; m++) {
        float c[8];
#pragma unroll
        for (int p = 0; p < 4; p++) unpack2(acc[m][p], c[2 * p], c[2 * p + 1]);
#pragma unroll
        for (int j = 0; j < 8; j++) c[j] += bias8[j];
        size_t o = (size_t)(m0 + tm + m) * G3 + n0 + tn;
        *(float4*)&xgout[o]     = make_float4(c[0], c[1], c[2], c[3]);
        *(float4*)&xgout[o + 4] = make_float4(c[4], c[5], c[6], c[7]);
    }
}

// ============================================================================
// Recurrent scan. grid = 64 CTAs: dir = bid&1 (dir 1 = reverse), 8 batch rows
// per CTA. 384 threads: thread owns gate columns {2*tid, 2*tid+1}.
// Per step:
//   phase1: hg[r][g] = bhh[g] + sum_k h[r][k]*whh[g][k]     (f32x2, row-pairs)
//   phase2: gates + h update, write output slice.
// h kept transposed in SMEM as h_s[k][r] so row-pairs load as ulonglong2.
// ============================================================================
__global__ void __launch_bounds__(384)
scan_kernel(const float* __restrict__ xg,
            const float* __restrict__ whhf, const float* __restrict__ whhr,
            const float* __restrict__ bhhf, const float* __restrict__ bhhr,
            float* __restrict__ rec, float* __restrict__ merged) {
    const int dir = blockIdx.x & 1;
    const int b0  = (blockIdx.x >> 1) * 8;
    const float* whh = dir ? whhr : whhf;
    const float* bhh = dir ? bhhr : bhhf;
    const float* xgd = xg + (size_t)dir * Mrows * G3;

    __shared__ __align__(16) float h_s[256][8];   // h transposed [k][r]
    __shared__ float hg_s[G3 * 9];                // [g][r] padded to 9

    const int tid = threadIdx.x;
    for (int i = tid; i < 2048; i += 384) ((float*)h_s)[i] = 0.f;

    const int g0 = 2 * tid;
    const float* wg0 = whh + (size_t)g0 * Hh;
    const float* wg1 = wg0 + Hh;
    const float bh0 = bhh[g0], bh1 = bhh[g0 + 1];
    const unsigned long long pb0 = pack2(bh0, bh0);
    const unsigned long long pb1 = pack2(bh1, bh1);
    __syncthreads();

    for (int step = 0; step < Tn; step++) {
        const int t = dir ? (Tn - 1 - step) : step;

        unsigned long long a0[4] = {pb0, pb0, pb0, pb0};
        unsigned long long a1[4] = {pb1, pb1, pb1, pb1};

        float4 w0 = *(const float4*)(wg0);
        float4 w1 = *(const float4*)(wg1);
        for (int k4 = 0; k4 < 64; k4++) {
            const int k  = k4 * 4;
            const int kn = (k4 < 63) ? k + 4 : 0;
            float4 nw0 = *(const float4*)(wg0 + kn);
            float4 nw1 = *(const float4*)(wg1 + kn);
            float w0v[4] = {w0.x, w0.y, w0.z, w0.w};
            float w1v[4] = {w1.x, w1.y, w1.z, w1.w};
#pragma unroll
            for (int kk = 0; kk < 4; kk++) {
                ulonglong2 hA = *(const ulonglong2*)&h_s[k + kk][0]; // rows (0,1),(2,3)
                ulonglong2 hB = *(const ulonglong2*)&h_s[k + kk][4]; // rows (4,5),(6,7)
                unsigned long long wr0 = pack2(w0v[kk], w0v[kk]);
                unsigned long long wr1 = pack2(w1v[kk], w1v[kk]);
                ffma2(a0[0], hA.x, wr0); ffma2(a0[1], hA.y, wr0);
                ffma2(a0[2], hB.x, wr0); ffma2(a0[3], hB.y, wr0);
                ffma2(a1[0], hA.x, wr1); ffma2(a1[1], hA.y, wr1);
                ffma2(a1[2], hB.x, wr1); ffma2(a1[3], hB.y, wr1);
            }
            w0 = nw0;
            w1 = nw1;
        }

#pragma unroll
        for (int p = 0; p < 4; p++) {
            float lo, hi;
            unpack2(a0[p], lo, hi);
            hg_s[g0 * 9 + 2 * p]     = lo;
            hg_s[g0 * 9 + 2 * p + 1] = hi;
            unpack2(a1[p], lo, hi);
            hg_s[(g0 + 1) * 9 + 2 * p]     = lo;
            hg_s[(g0 + 1) * 9 + 2 * p + 1] = hi;
        }
        __syncthreads();

        // phase 2: gates + update (2048 items)
        for (int idx = tid; idx < 2048; idx += 384) {
            const int r = idx >> 8;
            const int j = idx & 255;
            const int m = (b0 + r) * Tn + t;
            const float* xrow = xgd + (size_t)m * G3;
            float xr = xrow[j], xz = xrow[Hh + j], xn = xrow[2 * Hh + j];
            float hr = hg_s[j * 9 + r];
            float hz = hg_s[(Hh + j) * 9 + r];
            float hn = hg_s[(2 * Hh + j) * 9 + r];
            float rv = 1.f / (1.f + expf(-(xr + hr)));
            float zv = 1.f / (1.f + expf(-(xz + hz)));
            float nv = tanhf(xn + rv * hn);
            float hp = h_s[j][r];
            float hnw = (1.f - zv) * nv + zv * hp;
            h_s[j][r] = hnw;
            rec[(size_t)m * (2 * Hh) + dir * Hh + j] = hnw;
        }
        __syncthreads();
    }

    if (merged) {
        for (int idx = tid; idx < 2048; idx += 384) {
            const int r = idx >> 8;
            const int j = idx & 255;
            merged[(b0 + r) * (2 * Hh) + dir * Hh + j] = h_s[j][r];
        }
    }
}

// ============================================================================
// Attention + output. One CTA per batch row, 256 threads.
// ============================================================================
__global__ void __launch_bounds__(256)
attn_kernel(const float* __restrict__ rec2, const float* __restrict__ merged,
            float* __restrict__ out) {
    const int b   = blockIdx.x;
    const int tid = threadIdx.x;
    __shared__ __align__(16) float mg[512];
    __shared__ float sc[256];
    __shared__ float red[256];

    mg[tid]       = merged[b * 512 + tid];
    mg[tid + 256] = merged[b * 512 + 256 + tid];
    __syncthreads();

    // scores[t] = rec2[b,t,:] . merged[b,:]
    const float* base = rec2 + (size_t)b * Tn * 512;
    const float4* row = (const float4*)(base + (size_t)tid * 512);
    const float4* m4  = (const float4*)mg;
    float s = 0.f;
#pragma unroll 8
    for (int i = 0; i < 128; i++) {
        float4 a = row[i], c = m4[i];
        s += a.x * c.x + a.y * c.y + a.z * c.z + a.w * c.w;
    }
    sc[tid]  = s;
    red[tid] = s;
    __syncthreads();
    for (int off = 128; off; off >>= 1) {
        if (tid < off) red[tid] = fmaxf(red[tid], red[tid + off]);
        __syncthreads();
    }
    const float mx = red[0];
    __syncthreads();
    const float e = expf(s - mx);
    red[tid] = e;
    sc[tid]  = e;
    __syncthreads();
    for (int off = 128; off; off >>= 1) {
        if (tid < off) red[tid] += red[tid + off];
        __syncthreads();
    }
    const float inv = 1.f / red[0];
    __syncthreads();

    // attn[h] = sum_t rec2[b,t,h] * w[t]
    float acc0 = 0.f, acc1 = 0.f;
    for (int t = 0; t < Tn; t++) {
        const float w = sc[t] * inv;
        acc0 += base[(size_t)t * 512 + tid] * w;
        acc1 += base[(size_t)t * 512 + 256 + tid] * w;
    }
    float* ob = out + (size_t)b * 1024;
    ob[tid]       = acc0;
    ob[256 + tid] = acc1;
    ob[512 + tid] = base[(size_t)255 * 512 + tid];
    ob[768 + tid] = base[(size_t)255 * 512 + 256 + tid];
}

// ============================================================================
extern "C" void kernel_launch(void* const* d_in, const int* in_sizes, int n_in,
                              void* d_out, int out_size) {
    const float* input = (const float*)d_in[0];
    const float* wih1f = (const float*)d_in[1];
    const float* whh1f = (const float*)d_in[2];
    const float* bih1f = (const float*)d_in[3];
    const float* bhh1f = (const float*)d_in[4];
    const float* wih1r = (const float*)d_in[5];
    const float* whh1r = (const float*)d_in[6];
    const float* bih1r = (const float*)d_in[7];
    const float* bhh1r = (const float*)d_in[8];
    const float* wih2f = (const float*)d_in[9];
    const float* whh2f = (const float*)d_in[10];
    const float* bih2f = (const float*)d_in[11];
    const float* bhh2f = (const float*)d_in[12];
    const float* wih2r = (const float*)d_in[13];
    const float* whh2r = (const float*)d_in[14];
    const float* bih2r = (const float*)d_in[15];
    const float* bhh2r = (const float*)d_in[16];

    float *xg, *rec1, *rec2, *merged;
    cudaGetSymbolAddress((void**)&xg, g_xg);
    cudaGetSymbolAddress((void**)&rec1, g_rec1);
    cudaGetSymbolAddress((void**)&rec2, g_rec2);
    cudaGetSymbolAddress((void**)&merged, g_merged);

    // Layer 1
    igemm_kernel<NIN><<<dim3(12, 512), 256>>>(input, wih1f, wih1r, bih1f, bih1r, xg);
    scan_kernel<<<64, 384>>>(xg, whh1f, whh1r, bhh1f, bhh1r, rec1, nullptr);
    // Layer 2
    igemm_kernel<512><<<dim3(12, 512), 256>>>(rec1, wih2f, wih2r, bih2f, bih2r, xg);
    scan_kernel<<<64, 384>>>(xg, whh2f, whh2r, bhh2f, bhh2r, rec2, merged);
    // Attention + output
    attn_kernel<<<256, 256>>>(rec2, merged, (float*)d_out);
}

// round 14
// speedup vs baseline: 1.8591x; 1.8591x over previous
#include <cuda_runtime.h>
#include <cuda_bf16.h>
#include <math.h>

// Problem constants
static constexpr int Bn  = 256;   // batch
static constexpr int Tn  = 256;   // time
static constexpr int NIN = 128;
static constexpr int Hh  = 256;   // hidden
static constexpr int G3  = 768;   // 3*H
static constexpr int Mrows = Bn * Tn; // 65536

// ---------------- scratch (device globals; no allocation allowed) ----------
__device__ float g_xg[(size_t)2 * Mrows * G3];   // [dir][m][768]  (~403 MB)
__device__ float g_rec1[(size_t)Mrows * 2 * Hh]; // [m][512]
__device__ float g_rec2[(size_t)Mrows * 2 * Hh]; // [m][512]
__device__ float g_merged[Bn * 2 * Hh];          // [b][512]
__device__ float g_wpk[4][G3 * Hh];              // interleaved whh (l1f,l1r,l2f,l2r)

// ---------------- f32x2 packed-fp32 helpers (sm_103a) -----------------------
__device__ __forceinline__ unsigned long long pack2(float x, float y) {
    unsigned long long r;
    asm("mov.b64 %0, {%1, %2};" : "=l"(r) : "f"(x), "f"(y));
    return r;
}
__device__ __forceinline__ void unpack2(unsigned long long v, float& x, float& y) {
    asm("mov.b64 {%0, %1}, %2;" : "=f"(x), "=f"(y) : "l"(v));
}
__device__ __forceinline__ void ffma2(unsigned long long& d,
                                      unsigned long long a, unsigned long long b) {
    asm("fma.rn.f32x2 %0, %1, %2, %0;" : "+l"(d) : "l"(a), "l"(b));
}

// ============================================================================
// Weight interleave prep:
// wpk layout: element ((k4*2+plane)*384 + tid)*4 + kk  =  whh[(2*tid+plane)][4*k4+kk]
// so thread `tid` in the scan loads float4 {k..k+3} for its two gates with
// fully coalesced warp accesses (consecutive float4 across lanes).
// ============================================================================
__global__ void prep_weights(const float* __restrict__ w1f, const float* __restrict__ w1r,
                             const float* __restrict__ w2f, const float* __restrict__ w2r) {
    const float* srcs[4] = {w1f, w1r, w2f, w2r};
    int idx = blockIdx.x * blockDim.x + threadIdx.x; // 0 .. 4*196608-1
    if (idx >= 4 * G3 * Hh) return;
    int m = idx / (G3 * Hh);
    int r = idx % (G3 * Hh);
    int kk    = r & 3;
    int t3    = r >> 2;            // (k4*2+plane)*384 + tid
    int tid   = t3 % 384;
    int pp    = t3 / 384;
    int plane = pp & 1;
    int k4    = pp >> 1;
    int g     = 2 * tid + plane;
    int k     = 4 * k4 + kk;
    g_wpk[m][r] = srcs[m][g * Hh + k];
}

// ============================================================================
// Input-gate GEMM:
// xg[dir][m][g] = sum_k A[m][k] * W_dir[g][k] + bih_dir[g]
// ============================================================================
template <int K>
__global__ void __launch_bounds__(256, 2)
igemm_kernel(const float* __restrict__ A,
             const float* __restrict__ Wf, const float* __restrict__ Wr,
             const float* __restrict__ bf, const float* __restrict__ br,
             float* __restrict__ xg) {
    constexpr int KT = K / 16;
    const int nt  = blockIdx.x;
    const int dir = nt / 6;
    const int n0  = (nt % 6) * 128;
    const int m0  = blockIdx.y * 128;
    const float* W    = dir ? Wr : Wf;
    const float* bias = dir ? br : bf;
    float* xgout = xg + (size_t)dir * Mrows * G3;

    __shared__ __align__(16) float As[2][16][128];
    __shared__ __align__(16) float Ws[2][16][128];

    const int tid = threadIdx.x;
    const int tm  = (tid >> 4) << 3;
    const int tn  = (tid & 15) << 3;

    const int row0 = (tid) >> 2,        kq0 = (tid) & 3;
    const int row1 = (tid + 256) >> 2,  kq1 = (tid + 256) & 3;

    float4 ra0, ra1, rw0, rw1;
    auto ldg_tile = [&](int kt) {
        const float* ap = A + (size_t)(m0)*K + kt * 16;
        const float* wp = W + (size_t)(n0)*K + kt * 16;
        ra0 = *(const float4*)(ap + (size_t)row0 * K + kq0 * 4);
        ra1 = *(const float4*)(ap + (size_t)row1 * K + kq1 * 4);
        rw0 = *(const float4*)(wp + (size_t)row0 * K + kq0 * 4);
        rw1 = *(const float4*)(wp + (size_t)row1 * K + kq1 * 4);
    };
    auto sts_tile = [&](int s) {
        float a0v[4] = {ra0.x, ra0.y, ra0.z, ra0.w};
        float a1v[4] = {ra1.x, ra1.y, ra1.z, ra1.w};
        float w0v[4] = {rw0.x, rw0.y, rw0.z, rw0.w};
        float w1v[4] = {rw1.x, rw1.y, rw1.z, rw1.w};
#pragma unroll
        for (int j = 0; j < 4; j++) {
            As[s][kq0 * 4 + j][row0] = a0v[j];
            As[s][kq1 * 4 + j][row1] = a1v[j];
            Ws[s][kq0 * 4 + j][row0] = w0v[j];
            Ws[s][kq1 * 4 + j][row1] = w1v[j];
        }
    };

    unsigned long long acc[8][4];
#pragma unroll
    for (int m = 0; m < 8; m++)
#pragma unroll
        for (int p = 0; p < 4; p++) acc[m][p] = 0ull;

    ldg_tile(0);
    sts_tile(0);
    __syncthreads();

    int s = 0;
    for (int kt = 0; kt < KT; kt++) {
        if (kt + 1 < KT) ldg_tile(kt + 1);
#pragma unroll
        for (int k = 0; k < 16; k++) {
            float4 a0 = *(const float4*)&As[s][k][tm];
            float4 a1 = *(const float4*)&As[s][k][tm + 4];
            ulonglong2 b0 = *(const ulonglong2*)&Ws[s][k][tn];
            ulonglong2 b1 = *(const ulonglong2*)&Ws[s][k][tn + 4];
            float av[8] = {a0.x, a0.y, a0.z, a0.w, a1.x, a1.y, a1.z, a1.w};
#pragma unroll
            for (int m = 0; m < 8; m++) {
                unsigned long long ar = pack2(av[m], av[m]);
                ffma2(acc[m][0], ar, b0.x);
                ffma2(acc[m][1], ar, b0.y);
                ffma2(acc[m][2], ar, b1.x);
                ffma2(acc[m][3], ar, b1.y);
            }
        }
        if (kt + 1 < KT) {
            sts_tile(s ^ 1);
            __syncthreads();
            s ^= 1;
        }
    }

    float bias8[8];
#pragma unroll
    for (int j = 0; j < 8; j++) bias8[j] = bias[n0 + tn + j];

#pragma unroll
    for (int m = 0; m < 8; m++) {
        float c[8];
#pragma unroll
        for (int p = 0; p < 4; p++) unpack2(acc[m][p], c[2 * p], c[2 * p + 1]);
#pragma unroll
        for (int j = 0; j < 8; j++) c[j] += bias8[j];
        size_t o = (size_t)(m0 + tm + m) * G3 + n0 + tn;
        *(float4*)&xgout[o]     = make_float4(c[0], c[1], c[2], c[3]);
        *(float4*)&xgout[o + 4] = make_float4(c[4], c[5], c[6], c[7]);
    }
}

// ============================================================================
// Recurrent scan. 64 CTAs: dir = bid&1, 8 batch rows each. 384 threads,
// thread owns gates {2*tid, 2*tid+1}. Weights come from the interleaved
// g_wpk layout: per k4-chunk, two coalesced float4 loads per thread,
// prefetched 2 chunks ahead (covers L2 latency with ~160cyc/chunk of math).
// h kept transposed in SMEM as h_s[k][r] (warp-uniform broadcast reads).
// ============================================================================
__global__ void __launch_bounds__(384)
scan_kernel(const float* __restrict__ xg,
            const float* __restrict__ wpkf, const float* __restrict__ wpkr,
            const float* __restrict__ bhhf, const float* __restrict__ bhhr,
            float* __restrict__ rec, float* __restrict__ merged) {
    const int dir = blockIdx.x & 1;
    const int b0  = (blockIdx.x >> 1) * 8;
    const float4* wp = (const float4*)(dir ? wpkr : wpkf); // [k4][plane][384]
    const float* bhh = dir ? bhhr : bhhf;
    const float* xgd = xg + (size_t)dir * Mrows * G3;

    __shared__ __align__(16) float h_s[256][8];   // h transposed [k][r]
    __shared__ float hg_s[G3 * 9];                // [g][r] pad 9

    const int tid = threadIdx.x;
    for (int i = tid; i < 2048; i += 384) ((float*)h_s)[i] = 0.f;

    const int g0 = 2 * tid;
    const float bh0 = bhh[g0], bh1 = bhh[g0 + 1];
    const unsigned long long pb0 = pack2(bh0, bh0);
    const unsigned long long pb1 = pack2(bh1, bh1);
    __syncthreads();

    for (int step = 0; step < Tn; step++) {
        const int t = dir ? (Tn - 1 - step) : step;

        unsigned long long a0[4] = {pb0, pb0, pb0, pb0};
        unsigned long long a1[4] = {pb1, pb1, pb1, pb1};

        // 2-deep register prefetch pipeline over 64 k4-chunks
        float4 e0 = wp[tid],        o0 = wp[384 + tid];
        float4 e1 = wp[768 + tid],  o1 = wp[1152 + tid];
#pragma unroll 4
        for (int k4 = 0; k4 < 64; k4++) {
            float4 ce = e0, co = o0;
            e0 = e1; o0 = o1;
            if (k4 + 2 < 64) {
                e1 = wp[(k4 + 2) * 768 + tid];
                o1 = wp[(k4 + 2) * 768 + 384 + tid];
            }
            float ev[4] = {ce.x, ce.y, ce.z, ce.w};
            float ov[4] = {co.x, co.y, co.z, co.w};
            const int kb = k4 * 4;
#pragma unroll
            for (int kk = 0; kk < 4; kk++) {
                ulonglong2 hA = *(const ulonglong2*)&h_s[kb + kk][0];
                ulonglong2 hB = *(const ulonglong2*)&h_s[kb + kk][4];
                unsigned long long wr0 = pack2(ev[kk], ev[kk]);
                unsigned long long wr1 = pack2(ov[kk], ov[kk]);
                ffma2(a0[0], hA.x, wr0); ffma2(a0[1], hA.y, wr0);
                ffma2(a0[2], hB.x, wr0); ffma2(a0[3], hB.y, wr0);
                ffma2(a1[0], hA.x, wr1); ffma2(a1[1], hA.y, wr1);
                ffma2(a1[2], hB.x, wr1); ffma2(a1[3], hB.y, wr1);
            }
        }

#pragma unroll
        for (int p = 0; p < 4; p++) {
            float lo, hi;
            unpack2(a0[p], lo, hi);
            hg_s[g0 * 9 + 2 * p]     = lo;
            hg_s[g0 * 9 + 2 * p + 1] = hi;
            unpack2(a1[p], lo, hi);
            hg_s[(g0 + 1) * 9 + 2 * p]     = lo;
            hg_s[(g0 + 1) * 9 + 2 * p + 1] = hi;
        }
        __syncthreads();

        // phase 2: gates + h update (2048 items)
        for (int idx = tid; idx < 2048; idx += 384) {
            const int r = idx >> 8;
            const int j = idx & 255;
            const int m = (b0 + r) * Tn + t;
            const float* xrow = xgd + (size_t)m * G3;
            float xr = xrow[j], xz = xrow[Hh + j], xn = xrow[2 * Hh + j];
            float hr = hg_s[j * 9 + r];
            float hz = hg_s[(Hh + j) * 9 + r];
            float hn = hg_s[(2 * Hh + j) * 9 + r];
            float rv = 1.f / (1.f + expf(-(xr + hr)));
            float zv = 1.f / (1.f + expf(-(xz + hz)));
            float nv = tanhf(xn + rv * hn);
            float hp = h_s[j][r];
            float hnw = (1.f - zv) * nv + zv * hp;
            h_s[j][r] = hnw;
            rec[(size_t)m * (2 * Hh) + dir * Hh + j] = hnw;
        }
        __syncthreads();
    }

    if (merged) {
        for (int idx = tid; idx < 2048; idx += 384) {
            const int r = idx >> 8;
            const int j = idx & 255;
            merged[(b0 + r) * (2 * Hh) + dir * Hh + j] = h_s[j][r];
        }
    }
}

// ============================================================================
// Attention + output. One CTA per batch row, 256 threads.
// ============================================================================
__global__ void __launch_bounds__(256)
attn_kernel(const float* __restrict__ rec2, const float* __restrict__ merged,
            float* __restrict__ out) {
    const int b   = blockIdx.x;
    const int tid = threadIdx.x;
    __shared__ __align__(16) float mg[512];
    __shared__ float sc[256];
    __shared__ float red[256];

    mg[tid]       = merged[b * 512 + tid];
    mg[tid + 256] = merged[b * 512 + 256 + tid];
    __syncthreads();

    const float* base = rec2 + (size_t)b * Tn * 512;
    const float4* row = (const float4*)(base + (size_t)tid * 512);
    const float4* m4  = (const float4*)mg;
    float s = 0.f;
#pragma unroll 8
    for (int i = 0; i < 128; i++) {
        float4 a = row[i], c = m4[i];
        s += a.x * c.x + a.y * c.y + a.z * c.z + a.w * c.w;
    }
    sc[tid]  = s;
    red[tid] = s;
    __syncthreads();
    for (int off = 128; off; off >>= 1) {
        if (tid < off) red[tid] = fmaxf(red[tid], red[tid + off]);
        __syncthreads();
    }
    const float mx = red[0];
    __syncthreads();
    const float e = expf(s - mx);
    red[tid] = e;
    sc[tid]  = e;
    __syncthreads();
    for (int off = 128; off; off >>= 1) {
        if (tid < off) red[tid] += red[tid + off];
        __syncthreads();
    }
    const float inv = 1.f / red[0];
    __syncthreads();

    float acc0 = 0.f, acc1 = 0.f;
    for (int t = 0; t < Tn; t++) {
        const float w = sc[t] * inv;
        acc0 += base[(size_t)t * 512 + tid] * w;
        acc1 += base[(size_t)t * 512 + 256 + tid] * w;
    }
    float* ob = out + (size_t)b * 1024;
    ob[tid]       = acc0;
    ob[256 + tid] = acc1;
    ob[512 + tid] = base[(size_t)255 * 512 + tid];
    ob[768 + tid] = base[(size_t)255 * 512 + 256 + tid];
}

// ============================================================================
extern "C" void kernel_launch(void* const* d_in, const int* in_sizes, int n_in,
                              void* d_out, int out_size) {
    const float* input = (const float*)d_in[0];
    const float* wih1f = (const float*)d_in[1];
    const float* whh1f = (const float*)d_in[2];
    const float* bih1f = (const float*)d_in[3];
    const float* bhh1f = (const float*)d_in[4];
    const float* wih1r = (const float*)d_in[5];
    const float* whh1r = (const float*)d_in[6];
    const float* bih1r = (const float*)d_in[7];
    const float* bhh1r = (const float*)d_in[8];
    const float* wih2f = (const float*)d_in[9];
    const float* whh2f = (const float*)d_in[10];
    const float* bih2f = (const float*)d_in[11];
    const float* bhh2f = (const float*)d_in[12];
    const float* wih2r = (const float*)d_in[13];
    const float* whh2r = (const float*)d_in[14];
    const float* bih2r = (const float*)d_in[15];
    const float* bhh2r = (const float*)d_in[16];

    float *xg, *rec1, *rec2, *merged, *wpk;
    cudaGetSymbolAddress((void**)&xg, g_xg);
    cudaGetSymbolAddress((void**)&rec1, g_rec1);
    cudaGetSymbolAddress((void**)&rec2, g_rec2);
    cudaGetSymbolAddress((void**)&merged, g_merged);
    cudaGetSymbolAddress((void**)&wpk, g_wpk);

    // Interleave all 4 recurrent weight matrices for coalesced scan loads
    prep_weights<<<(4 * G3 * Hh + 255) / 256, 256>>>(whh1f, whh1r, whh2f, whh2r);

    // Layer 1
    igemm_kernel<NIN><<<dim3(12, 512), 256>>>(input, wih1f, wih1r, bih1f, bih1r, xg);
    scan_kernel<<<64, 384>>>(xg, wpk + 0 * (G3 * Hh), wpk + 1 * (G3 * Hh),
                             bhh1f, bhh1r, rec1, nullptr);
    // Layer 2
    igemm_kernel<512><<<dim3(12, 512), 256>>>(rec1, wih2f, wih2r, bih2f, bih2r, xg);
    scan_kernel<<<64, 384>>>(xg, wpk + 2 * (G3 * Hh), wpk + 3 * (G3 * Hh),
                             bhh2f, bhh2r, rec2, merged);
    // Attention + output
    attn_kernel<<<256, 256>>>(rec2, merged, (float*)d_out);
}

// round 15
// speedup vs baseline: 2.0754x; 1.1163x over previous
#include <cuda_runtime.h>
#include <cuda_bf16.h>
#include <math.h>

// Problem constants
static constexpr int Bn  = 256;   // batch
static constexpr int Tn  = 256;   // time
static constexpr int NIN = 128;
static constexpr int Hh  = 256;   // hidden
static constexpr int G3  = 768;   // 3*H
static constexpr int Mrows = Bn * Tn; // 65536

// ---------------- scratch (device globals; no allocation allowed) ----------
__device__ float g_xg[(size_t)2 * Mrows * G3];   // [dir][m][768]  (~403 MB)
__device__ float g_rec1[(size_t)Mrows * 2 * Hh]; // [m][512]
__device__ float g_rec2[(size_t)Mrows * 2 * Hh]; // [m][512]
__device__ float g_merged[Bn * 2 * Hh];          // [b][512]
__device__ float g_wpk[4][G3 * Hh];              // interleaved whh (l1f,l1r,l2f,l2r)

// ---------------- f32x2 packed-fp32 helpers (sm_103a) -----------------------
__device__ __forceinline__ unsigned long long pack2(float x, float y) {
    unsigned long long r;
    asm("mov.b64 %0, {%1, %2};" : "=l"(r) : "f"(x), "f"(y));
    return r;
}
__device__ __forceinline__ void unpack2(unsigned long long v, float& x, float& y) {
    asm("mov.b64 {%0, %1}, %2;" : "=f"(x), "=f"(y) : "l"(v));
}
__device__ __forceinline__ void ffma2(unsigned long long& d,
                                      unsigned long long a, unsigned long long b) {
    asm("fma.rn.f32x2 %0, %1, %2, %0;" : "+l"(d) : "l"(a), "l"(b));
}

// ---------------- cluster helpers ------------------------------------------
__device__ __forceinline__ unsigned smem_u32(const void* p) {
    unsigned a;
    asm("{ .reg .u64 t; cvta.to.shared.u64 t, %1; cvt.u32.u64 %0, t; }"
        : "=r"(a) : "l"(p));
    return a;
}
__device__ __forceinline__ unsigned cluster_rank() {
    unsigned r;
    asm("mov.u32 %0, %%cluster_ctarank;" : "=r"(r));
    return r;
}
__device__ __forceinline__ void sts_cluster_f32(unsigned laddr, unsigned peer, float v) {
    asm volatile(
        "{ .reg .b32 ra; mapa.shared::cluster.u32 ra, %0, %1; "
        "st.shared::cluster.f32 [ra], %2; }"
        :: "r"(laddr), "r"(peer), "f"(v) : "memory");
}
#define CLUSTER_SYNC() do { \
    asm volatile("barrier.cluster.arrive.aligned;" ::: "memory"); \
    asm volatile("barrier.cluster.wait.aligned;"   ::: "memory"); \
} while (0)

// ============================================================================
// Weight interleave prep (cluster-split layout):
// float4 index within a matrix: rank*(64*384) + k4*384 + tid
//   holds whh[g][4*k4 .. 4*k4+3] where g = (tid/128)*256 + rank*128 + (tid%128)
// so scan thread `tid` of cluster-rank `rank` loads ONE coalesced float4/chunk.
// ============================================================================
__global__ void prep_weights(const float* __restrict__ w1f, const float* __restrict__ w1r,
                             const float* __restrict__ w2f, const float* __restrict__ w2r) {
    const float* srcs[4] = {w1f, w1r, w2f, w2r};
    int idx = blockIdx.x * blockDim.x + threadIdx.x; // 0 .. 4*196608-1
    if (idx >= 4 * G3 * Hh) return;
    int m = idx / (G3 * Hh);
    int r = idx % (G3 * Hh);
    int kk   = r & 3;
    int u    = r >> 2;          // rank*24576 + k4*384 + tid
    int tid  = u % 384;
    int w    = u / 384;         // rank*64 + k4
    int k4   = w & 63;
    int rank = w >> 6;
    int g    = (tid >> 7) * 256 + rank * 128 + (tid & 127);
    int k    = 4 * k4 + kk;
    g_wpk[m][r] = srcs[m][g * Hh + k];
}

// ============================================================================
// Input-gate GEMM (unchanged from R14 pass):
// xg[dir][m][g] = sum_k A[m][k] * W_dir[g][k] + bih_dir[g]
// ============================================================================
template <int K>
__global__ void __launch_bounds__(256, 2)
igemm_kernel(const float* __restrict__ A,
             const float* __restrict__ Wf, const float* __restrict__ Wr,
             const float* __restrict__ bf, const float* __restrict__ br,
             float* __restrict__ xg) {
    constexpr int KT = K / 16;
    const int nt  = blockIdx.x;
    const int dir = nt / 6;
    const int n0  = (nt % 6) * 128;
    const int m0  = blockIdx.y * 128;
    const float* W    = dir ? Wr : Wf;
    const float* bias = dir ? br : bf;
    float* xgout = xg + (size_t)dir * Mrows * G3;

    __shared__ __align__(16) float As[2][16][128];
    __shared__ __align__(16) float Ws[2][16][128];

    const int tid = threadIdx.x;
    const int tm  = (tid >> 4) << 3;
    const int tn  = (tid & 15) << 3;

    const int row0 = (tid) >> 2,        kq0 = (tid) & 3;
    const int row1 = (tid + 256) >> 2,  kq1 = (tid + 256) & 3;

    float4 ra0, ra1, rw0, rw1;
    auto ldg_tile = [&](int kt) {
        const float* ap = A + (size_t)(m0)*K + kt * 16;
        const float* wp = W + (size_t)(n0)*K + kt * 16;
        ra0 = *(const float4*)(ap + (size_t)row0 * K + kq0 * 4);
        ra1 = *(const float4*)(ap + (size_t)row1 * K + kq1 * 4);
        rw0 = *(const float4*)(wp + (size_t)row0 * K + kq0 * 4);
        rw1 = *(const float4*)(wp + (size_t)row1 * K + kq1 * 4);
    };
    auto sts_tile = [&](int s) {
        float a0v[4] = {ra0.x, ra0.y, ra0.z, ra0.w};
        float a1v[4] = {ra1.x, ra1.y, ra1.z, ra1.w};
        float w0v[4] = {rw0.x, rw0.y, rw0.z, rw0.w};
        float w1v[4] = {rw1.x, rw1.y, rw1.z, rw1.w};
#pragma unroll
        for (int j = 0; j < 4; j++) {
            As[s][kq0 * 4 + j][row0] = a0v[j];
            As[s][kq1 * 4 + j][row1] = a1v[j];
            Ws[s][kq0 * 4 + j][row0] = w0v[j];
            Ws[s][kq1 * 4 + j][row1] = w1v[j];
        }
    };

    unsigned long long acc[8][4];
#pragma unroll
    for (int m = 0; m < 8; m++)
#pragma unroll
        for (int p = 0; p < 4; p++) acc[m][p] = 0ull;

    ldg_tile(0);
    sts_tile(0);
    __syncthreads();

    int s = 0;
    for (int kt = 0; kt < KT; kt++) {
        if (kt + 1 < KT) ldg_tile(kt + 1);
#pragma unroll
        for (int k = 0; k < 16; k++) {
            float4 a0 = *(const float4*)&As[s][k][tm];
            float4 a1 = *(const float4*)&As[s][k][tm + 4];
            ulonglong2 b0 = *(const ulonglong2*)&Ws[s][k][tn];
            ulonglong2 b1 = *(const ulonglong2*)&Ws[s][k][tn + 4];
            float av[8] = {a0.x, a0.y, a0.z, a0.w, a1.x, a1.y, a1.z, a1.w};
#pragma unroll
            for (int m = 0; m < 8; m++) {
                unsigned long long ar = pack2(av[m], av[m]);
                ffma2(acc[m][0], ar, b0.x);
                ffma2(acc[m][1], ar, b0.y);
                ffma2(acc[m][2], ar, b1.x);
                ffma2(acc[m][3], ar, b1.y);
            }
        }
        if (kt + 1 < KT) {
            sts_tile(s ^ 1);
            __syncthreads();
            s ^= 1;
        }
    }

    float bias8[8];
#pragma unroll
    for (int j = 0; j < 8; j++) bias8[j] = bias[n0 + tn + j];

#pragma unroll
    for (int m = 0; m < 8; m++) {
        float c[8];
#pragma unroll
        for (int p = 0; p < 4; p++) unpack2(acc[m][p], c[2 * p], c[2 * p + 1]);
#pragma unroll
        for (int j = 0; j < 8; j++) c[j] += bias8[j];
        size_t o = (size_t)(m0 + tm + m) * G3 + n0 + tn;
        *(float4*)&xgout[o]     = make_float4(c[0], c[1], c[2], c[3]);
        *(float4*)&xgout[o + 4] = make_float4(c[4], c[5], c[6], c[7]);
    }
}

// ============================================================================
// Recurrent scan, cluster-split. 128 CTAs = 64 clusters of 2.
// cluster c: dir = c&1, rows b0..b0+7 (b0 = (c>>1)*8). Within cluster,
// rank handles hidden half j in [rank*128, rank*128+128): its 384 gates
// (r/z/n for those j), its phase-2 h-updates, and pushes updated h to the
// peer via DSMEM. h double-buffered; one cluster barrier per step.
// Per-CTA FMA halves vs R14 (1024 ffma2/thread/step); weight restream
// halves per CTA (393KB/step); chip L2 traffic unchanged.
// ============================================================================
__global__ void __launch_bounds__(384) __cluster_dims__(2, 1, 1)
scan_kernel(const float* __restrict__ xg,
            const float* __restrict__ wpkf, const float* __restrict__ wpkr,
            const float* __restrict__ bhhf, const float* __restrict__ bhhr,
            float* __restrict__ rec, float* __restrict__ merged) {
    const int c   = blockIdx.x >> 1;
    const int dir = c & 1;
    const int b0  = (c >> 1) * 8;
    const unsigned rank = cluster_rank();
    const unsigned peer = rank ^ 1u;

    const float* wsel = dir ? wpkr : wpkf;
    const float4* wp4 = (const float4*)wsel + (size_t)rank * (64 * 384);
    const float* bhh  = dir ? bhhr : bhhf;
    const float* xgd  = xg + (size_t)dir * Mrows * G3;

    __shared__ __align__(16) float h_s[2][256][8]; // double-buffered h, [k][r]
    __shared__ float hg_s[384 * 9];                // this CTA's 384 gates, pad 9

    const int tid = threadIdx.x;
    for (int i = tid; i < 2 * 2048; i += 384) ((float*)h_s)[i] = 0.f;

    // this thread's single gate: g = q*256 + rank*128 + jl
    const int jl = tid & 127;
    const int g  = (tid >> 7) * 256 + (int)rank * 128 + jl;
    const float bh = bhh[g];
    const unsigned long long pb = pack2(bh, bh);

    // peer may DSMEM-write our h_s during step 0 — both CTAs must finish init
    CLUSTER_SYNC();

    int cur = 0;
    for (int step = 0; step < Tn; step++) {
        const int t  = dir ? (Tn - 1 - step) : step;
        const int nb = cur ^ 1;

        unsigned long long a[4] = {pb, pb, pb, pb};

        // 4-deep register prefetch over 64 k4-chunks (1 float4/chunk)
        float4 w0 = wp4[tid], w1 = wp4[384 + tid];
        float4 w2 = wp4[768 + tid], w3 = wp4[1152 + tid];
#pragma unroll 4
        for (int k4 = 0; k4 < 64; k4++) {
            float4 cw = w0; w0 = w1; w1 = w2; w2 = w3;
            if (k4 + 4 < 64) w3 = wp4[(k4 + 4) * 384 + tid];
            float wv[4] = {cw.x, cw.y, cw.z, cw.w};
            const int kb = k4 * 4;
#pragma unroll
            for (int kk = 0; kk < 4; kk++) {
                ulonglong2 hA = *(const ulonglong2*)&h_s[cur][kb + kk][0];
                ulonglong2 hB = *(const ulonglong2*)&h_s[cur][kb + kk][4];
                unsigned long long wr = pack2(wv[kk], wv[kk]);
                ffma2(a[0], hA.x, wr); ffma2(a[1], hA.y, wr);
                ffma2(a[2], hB.x, wr); ffma2(a[3], hB.y, wr);
            }
        }

#pragma unroll
        for (int p = 0; p < 4; p++) {
            float lo, hi;
            unpack2(a[p], lo, hi);
            hg_s[tid * 9 + 2 * p]     = lo;
            hg_s[tid * 9 + 2 * p + 1] = hi;
        }
        __syncthreads();

        // phase 2: 1024 items (128 j-half x 8 rows)
        for (int idx = tid; idx < 1024; idx += 384) {
            const int r  = idx >> 7;
            const int jj = idx & 127;
            const int jg = (int)rank * 128 + jj;
            const int m  = (b0 + r) * Tn + t;
            const float* xrow = xgd + (size_t)m * G3;
            float xr = xrow[jg], xz = xrow[Hh + jg], xn = xrow[2 * Hh + jg];
            float hr = hg_s[jj * 9 + r];
            float hz = hg_s[(128 + jj) * 9 + r];
            float hn = hg_s[(256 + jj) * 9 + r];
            float rv = 1.f / (1.f + expf(-(xr + hr)));
            float zv = 1.f / (1.f + expf(-(xz + hz)));
            float nv = tanhf(xn + rv * hn);
            float hp = h_s[cur][jg][r];
            float hnw = (1.f - zv) * nv + zv * hp;
            h_s[nb][jg][r] = hnw;
            sts_cluster_f32(smem_u32(&h_s[nb][jg][r]), peer, hnw);
            rec[(size_t)m * (2 * Hh) + dir * Hh + jg] = hnw;
        }

        // release our DSMEM writes / acquire peer's before next phase 1
        CLUSTER_SYNC();
        cur = nb;
    }

    if (merged) {
        for (int idx = tid; idx < 1024; idx += 384) {
            const int r  = idx >> 7;
            const int jj = idx & 127;
            const int jg = (int)rank * 128 + jj;
            merged[(b0 + r) * (2 * Hh) + dir * Hh + jg] = h_s[cur][jg][r];
        }
    }
}

// ============================================================================
// Attention + output. One CTA per batch row, 256 threads. (unchanged)
// ============================================================================
__global__ void __launch_bounds__(256)
attn_kernel(const float* __restrict__ rec2, const float* __restrict__ merged,
            float* __restrict__ out) {
    const int b   = blockIdx.x;
    const int tid = threadIdx.x;
    __shared__ __align__(16) float mg[512];
    __shared__ float sc[256];
    __shared__ float red[256];

    mg[tid]       = merged[b * 512 + tid];
    mg[tid + 256] = merged[b * 512 + 256 + tid];
    __syncthreads();

    const float* base = rec2 + (size_t)b * Tn * 512;
    const float4* row = (const float4*)(base + (size_t)tid * 512);
    const float4* m4  = (const float4*)mg;
    float s = 0.f;
#pragma unroll 8
    for (int i = 0; i < 128; i++) {
        float4 a = row[i], c = m4[i];
        s += a.x * c.x + a.y * c.y + a.z * c.z + a.w * c.w;
    }
    sc[tid]  = s;
    red[tid] = s;
    __syncthreads();
    for (int off = 128; off; off >>= 1) {
        if (tid < off) red[tid] = fmaxf(red[tid], red[tid + off]);
        __syncthreads();
    }
    const float mx = red[0];
    __syncthreads();
    const float e = expf(s - mx);
    red[tid] = e;
    sc[tid]  = e;
    __syncthreads();
    for (int off = 128; off; off >>= 1) {
        if (tid < off) red[tid] += red[tid + off];
        __syncthreads();
    }
    const float inv = 1.f / red[0];
    __syncthreads();

    float acc0 = 0.f, acc1 = 0.f;
    for (int t = 0; t < Tn; t++) {
        const float w = sc[t] * inv;
        acc0 += base[(size_t)t * 512 + tid] * w;
        acc1 += base[(size_t)t * 512 + 256 + tid] * w;
    }
    float* ob = out + (size_t)b * 1024;
    ob[tid]       = acc0;
    ob[256 + tid] = acc1;
    ob[512 + tid] = base[(size_t)255 * 512 + tid];
    ob[768 + tid] = base[(size_t)255 * 512 + 256 + tid];
}

// ============================================================================
extern "C" void kernel_launch(void* const* d_in, const int* in_sizes, int n_in,
                              void* d_out, int out_size) {
    const float* input = (const float*)d_in[0];
    const float* wih1f = (const float*)d_in[1];
    const float* whh1f = (const float*)d_in[2];
    const float* bih1f = (const float*)d_in[3];
    const float* bhh1f = (const float*)d_in[4];
    const float* wih1r = (const float*)d_in[5];
    const float* whh1r = (const float*)d_in[6];
    const float* bih1r = (const float*)d_in[7];
    const float* bhh1r = (const float*)d_in[8];
    const float* wih2f = (const float*)d_in[9];
    const float* whh2f = (const float*)d_in[10];
    const float* bih2f = (const float*)d_in[11];
    const float* bhh2f = (const float*)d_in[12];
    const float* wih2r = (const float*)d_in[13];
    const float* whh2r = (const float*)d_in[14];
    const float* bih2r = (const float*)d_in[15];
    const float* bhh2r = (const float*)d_in[16];

    float *xg, *rec1, *rec2, *merged, *wpk;
    cudaGetSymbolAddress((void**)&xg, g_xg);
    cudaGetSymbolAddress((void**)&rec1, g_rec1);
    cudaGetSymbolAddress((void**)&rec2, g_rec2);
    cudaGetSymbolAddress((void**)&merged, g_merged);
    cudaGetSymbolAddress((void**)&wpk, g_wpk);

    // Interleave all 4 recurrent weight matrices (cluster-split layout)
    prep_weights<<<(4 * G3 * Hh + 255) / 256, 256>>>(whh1f, whh1r, whh2f, whh2r);

    // Layer 1
    igemm_kernel<NIN><<<dim3(12, 512), 256>>>(input, wih1f, wih1r, bih1f, bih1r, xg);
    scan_kernel<<<128, 384>>>(xg, wpk + 0 * (G3 * Hh), wpk + 1 * (G3 * Hh),
                              bhh1f, bhh1r, rec1, nullptr);
    // Layer 2
    igemm_kernel<512><<<dim3(12, 512), 256>>>(rec1, wih2f, wih2r, bih2f, bih2r, xg);
    scan_kernel<<<128, 384>>>(xg, wpk + 2 * (G3 * Hh), wpk + 3 * (G3 * Hh),
                              bhh2f, bhh2r, rec2, merged);
    // Attention + output
    attn_kernel<<<256, 256>>>(rec2, merged, (float*)d_out);
}

// round 17
// speedup vs baseline: 2.1367x; 1.0296x over previous
#include <cuda_runtime.h>
#include <cuda_bf16.h>
#include <math.h>

// Problem constants
static constexpr int Bn  = 256;   // batch
static constexpr int Tn  = 256;   // time
static constexpr int NIN = 128;
static constexpr int Hh  = 256;   // hidden
static constexpr int G3  = 768;   // 3*H
static constexpr int Mrows = Bn * Tn; // 65536

// ---------------- scratch (device globals; no allocation allowed) ----------
__device__ float g_xg[(size_t)2 * Mrows * G3];   // [dir][m][768]  (~403 MB)
__device__ float g_rec1[(size_t)Mrows * 2 * Hh]; // [m][512]
__device__ float g_rec2[(size_t)Mrows * 2 * Hh]; // [m][512]
__device__ float g_merged[Bn * 2 * Hh];          // [b][512]
__device__ float g_wpk[4][G3 * Hh];              // interleaved whh (l1f,l1r,l2f,l2r)

// ---------------- f32x2 packed-fp32 helpers (sm_103a) -----------------------
__device__ __forceinline__ unsigned long long pack2(float x, float y) {
    unsigned long long r;
    asm("mov.b64 %0, {%1, %2};" : "=l"(r) : "f"(x), "f"(y));
    return r;
}
__device__ __forceinline__ void unpack2(unsigned long long v, float& x, float& y) {
    asm("mov.b64 {%0, %1}, %2;" : "=f"(x), "=f"(y) : "l"(v));
}
__device__ __forceinline__ void ffma2(unsigned long long& d,
                                      unsigned long long a, unsigned long long b) {
    asm("fma.rn.f32x2 %0, %1, %2, %0;" : "+l"(d) : "l"(a), "l"(b));
}

// ---------------- cluster helpers ------------------------------------------
__device__ __forceinline__ unsigned smem_u32(const void* p) {
    unsigned a;
    asm("{ .reg .u64 t; cvta.to.shared.u64 t, %1; cvt.u32.u64 %0, t; }"
        : "=r"(a) : "l"(p));
    return a;
}
__device__ __forceinline__ unsigned cluster_rank() {
    unsigned r;
    asm("mov.u32 %0, %%cluster_ctarank;" : "=r"(r));
    return r;
}
__device__ __forceinline__ void sts_cluster_f32(unsigned laddr, unsigned peer, float v) {
    asm volatile(
        "{ .reg .b32 ra; mapa.shared::cluster.u32 ra, %0, %1; "
        "st.shared::cluster.f32 [ra], %2; }"
        :: "r"(laddr), "r"(peer), "f"(v) : "memory");
}
#define CLUSTER_SYNC() do { \
    asm volatile("barrier.cluster.arrive.aligned;" ::: "memory"); \
    asm volatile("barrier.cluster.wait.aligned;"   ::: "memory"); \
} while (0)

// ============================================================================
// Weight interleave prep (cluster-split layout, identical to R15-passing):
// float4 index within a matrix: rank*(64*384) + k4*384 + gl
//   holds whh[g][4*k4 .. 4*k4+3] where g = (gl/128)*256 + rank*128 + (gl%128)
// ============================================================================
__global__ void prep_weights(const float* __restrict__ w1f, const float* __restrict__ w1r,
                             const float* __restrict__ w2f, const float* __restrict__ w2r) {
    const float* srcs[4] = {w1f, w1r, w2f, w2r};
    int idx = blockIdx.x * blockDim.x + threadIdx.x; // 0 .. 4*196608-1
    if (idx >= 4 * G3 * Hh) return;
    int m = idx / (G3 * Hh);
    int r = idx % (G3 * Hh);
    int kk   = r & 3;
    int u    = r >> 2;          // rank*24576 + k4*384 + gl
    int gl   = u % 384;
    int w    = u / 384;         // rank*64 + k4
    int k4   = w & 63;
    int rank = w >> 6;
    int g    = (gl >> 7) * 256 + rank * 128 + (gl & 127);
    int k    = 4 * k4 + kk;
    g_wpk[m][r] = srcs[m][g * Hh + k];
}

// ============================================================================
// Input-gate GEMM with conflict-free SMEM column permutation:
// column c (0..127) stored at p(c) = ((c&4)<<4) + ((c>>3)<<2) + (c&3),
// row padded to 132 floats. Each thread's 8 columns become two contiguous
// float4 runs at [tm>>1] and [64+(tm>>1)] -> lanes read at 16B stride,
// conflict-free per LDS.128 phase.
// ============================================================================
template <int K>
__global__ void __launch_bounds__(256, 2)
igemm_kernel(const float* __restrict__ A,
             const float* __restrict__ Wf, const float* __restrict__ Wr,
             const float* __restrict__ bf, const float* __restrict__ br,
             float* __restrict__ xg) {
    constexpr int KT = K / 16;
    const int nt  = blockIdx.x;
    const int dir = nt / 6;
    const int n0  = (nt % 6) * 128;
    const int m0  = blockIdx.y * 128;
    const float* W    = dir ? Wr : Wf;
    const float* bias = dir ? br : bf;
    float* xgout = xg + (size_t)dir * Mrows * G3;

    __shared__ __align__(16) float As[2][16][132];
    __shared__ __align__(16) float Ws[2][16][132];

    const int tid = threadIdx.x;
    const int tm  = (tid >> 4) << 3;
    const int tn  = (tid & 15) << 3;

    const int row0 = (tid) >> 2,        kq0 = (tid) & 3;
    const int row1 = (tid + 256) >> 2,  kq1 = (tid + 256) & 3;
    // permuted store columns
    const int pr0 = ((row0 & 4) << 4) + ((row0 >> 3) << 2) + (row0 & 3);
    const int pr1 = ((row1 & 4) << 4) + ((row1 >> 3) << 2) + (row1 & 3);

    float4 ra0, ra1, rw0, rw1;
    auto ldg_tile = [&](int kt) {
        const float* ap = A + (size_t)(m0)*K + kt * 16;
        const float* wp = W + (size_t)(n0)*K + kt * 16;
        ra0 = *(const float4*)(ap + (size_t)row0 * K + kq0 * 4);
        ra1 = *(const float4*)(ap + (size_t)row1 * K + kq1 * 4);
        rw0 = *(const float4*)(wp + (size_t)row0 * K + kq0 * 4);
        rw1 = *(const float4*)(wp + (size_t)row1 * K + kq1 * 4);
    };
    auto sts_tile = [&](int s) {
        float a0v[4] = {ra0.x, ra0.y, ra0.z, ra0.w};
        float a1v[4] = {ra1.x, ra1.y, ra1.z, ra1.w};
        float w0v[4] = {rw0.x, rw0.y, rw0.z, rw0.w};
        float w1v[4] = {rw1.x, rw1.y, rw1.z, rw1.w};
#pragma unroll
        for (int j = 0; j < 4; j++) {
            As[s][kq0 * 4 + j][pr0] = a0v[j];
            As[s][kq1 * 4 + j][pr1] = a1v[j];
            Ws[s][kq0 * 4 + j][pr0] = w0v[j];
            Ws[s][kq1 * 4 + j][pr1] = w1v[j];
        }
    };

    unsigned long long acc[8][4];
#pragma unroll
    for (int m = 0; m < 8; m++)
#pragma unroll
        for (int p = 0; p < 4; p++) acc[m][p] = 0ull;

    ldg_tile(0);
    sts_tile(0);
    __syncthreads();

    const int tmh = tm >> 1;   // permuted base for m-cols
    const int tnh = tn >> 1;   // permuted base for n-cols

    int s = 0;
    for (int kt = 0; kt < KT; kt++) {
        if (kt + 1 < KT) ldg_tile(kt + 1);
#pragma unroll
        for (int k = 0; k < 16; k++) {
            float4 a0 = *(const float4*)&As[s][k][tmh];
            float4 a1 = *(const float4*)&As[s][k][64 + tmh];
            ulonglong2 b0 = *(const ulonglong2*)&Ws[s][k][tnh];
            ulonglong2 b1 = *(const ulonglong2*)&Ws[s][k][64 + tnh];
            float av[8] = {a0.x, a0.y, a0.z, a0.w, a1.x, a1.y, a1.z, a1.w};
#pragma unroll
            for (int m = 0; m < 8; m++) {
                unsigned long long ar = pack2(av[m], av[m]);
                ffma2(acc[m][0], ar, b0.x);
                ffma2(acc[m][1], ar, b0.y);
                ffma2(acc[m][2], ar, b1.x);
                ffma2(acc[m][3], ar, b1.y);
            }
        }
        if (kt + 1 < KT) {
            sts_tile(s ^ 1);
            __syncthreads();
            s ^= 1;
        }
    }

    float bias8[8];
#pragma unroll
    for (int j = 0; j < 8; j++) bias8[j] = bias[n0 + tn + j];

#pragma unroll
    for (int m = 0; m < 8; m++) {
        float c[8];
#pragma unroll
        for (int p = 0; p < 4; p++) unpack2(acc[m][p], c[2 * p], c[2 * p + 1]);
#pragma unroll
        for (int j = 0; j < 8; j++) c[j] += bias8[j];
        size_t o = (size_t)(m0 + tm + m) * G3 + n0 + tn;
        *(float4*)&xgout[o]     = make_float4(c[0], c[1], c[2], c[3]);
        *(float4*)&xgout[o + 4] = make_float4(c[4], c[5], c[6], c[7]);
    }
}

// ============================================================================
// Recurrent scan — EXACT R15-passing version. 128 CTAs = 64 clusters of 2,
// 384 threads. rank handles hidden half j in [rank*128, rank*128+128):
// its 384 gates, phase-2 h-updates, peer push via DSMEM. h double-buffered;
// one cluster barrier per step.
// ============================================================================
__global__ void __launch_bounds__(384) __cluster_dims__(2, 1, 1)
scan_kernel(const float* __restrict__ xg,
            const float* __restrict__ wpkf, const float* __restrict__ wpkr,
            const float* __restrict__ bhhf, const float* __restrict__ bhhr,
            float* __restrict__ rec, float* __restrict__ merged) {
    const int c   = blockIdx.x >> 1;
    const int dir = c & 1;
    const int b0  = (c >> 1) * 8;
    const unsigned rank = cluster_rank();
    const unsigned peer = rank ^ 1u;

    const float* wsel = dir ? wpkr : wpkf;
    const float4* wp4 = (const float4*)wsel + (size_t)rank * (64 * 384);
    const float* bhh  = dir ? bhhr : bhhf;
    const float* xgd  = xg + (size_t)dir * Mrows * G3;

    __shared__ __align__(16) float h_s[2][256][8]; // double-buffered h, [k][r]
    __shared__ float hg_s[384 * 9];                // this CTA's 384 gates, pad 9

    const int tid = threadIdx.x;
    for (int i = tid; i < 2 * 2048; i += 384) ((float*)h_s)[i] = 0.f;

    // this thread's single gate: g = q*256 + rank*128 + jl
    const int jl = tid & 127;
    const int g  = (tid >> 7) * 256 + (int)rank * 128 + jl;
    const float bh = bhh[g];
    const unsigned long long pb = pack2(bh, bh);

    // peer may DSMEM-write our h_s during step 0 — both CTAs must finish init
    CLUSTER_SYNC();

    int cur = 0;
    for (int step = 0; step < Tn; step++) {
        const int t  = dir ? (Tn - 1 - step) : step;
        const int nb = cur ^ 1;

        unsigned long long a[4] = {pb, pb, pb, pb};

        // 4-deep register prefetch over 64 k4-chunks (1 float4/chunk)
        float4 w0 = wp4[tid], w1 = wp4[384 + tid];
        float4 w2 = wp4[768 + tid], w3 = wp4[1152 + tid];
#pragma unroll 4
        for (int k4 = 0; k4 < 64; k4++) {
            float4 cw = w0; w0 = w1; w1 = w2; w2 = w3;
            if (k4 + 4 < 64) w3 = wp4[(k4 + 4) * 384 + tid];
            float wv[4] = {cw.x, cw.y, cw.z, cw.w};
            const int kb = k4 * 4;
#pragma unroll
            for (int kk = 0; kk < 4; kk++) {
                ulonglong2 hA = *(const ulonglong2*)&h_s[cur][kb + kk][0];
                ulonglong2 hB = *(const ulonglong2*)&h_s[cur][kb + kk][4];
                unsigned long long wr = pack2(wv[kk], wv[kk]);
                ffma2(a[0], hA.x, wr); ffma2(a[1], hA.y, wr);
                ffma2(a[2], hB.x, wr); ffma2(a[3], hB.y, wr);
            }
        }

#pragma unroll
        for (int p = 0; p < 4; p++) {
            float lo, hi;
            unpack2(a[p], lo, hi);
            hg_s[tid * 9 + 2 * p]     = lo;
            hg_s[tid * 9 + 2 * p + 1] = hi;
        }
        __syncthreads();

        // phase 2: 1024 items (128 j-half x 8 rows)
        for (int idx = tid; idx < 1024; idx += 384) {
            const int r  = idx >> 7;
            const int jj = idx & 127;
            const int jg = (int)rank * 128 + jj;
            const int m  = (b0 + r) * Tn + t;
            const float* xrow = xgd + (size_t)m * G3;
            float xr = xrow[jg], xz = xrow[Hh + jg], xn = xrow[2 * Hh + jg];
            float hr = hg_s[jj * 9 + r];
            float hz = hg_s[(128 + jj) * 9 + r];
            float hn = hg_s[(256 + jj) * 9 + r];
            float rv = 1.f / (1.f + expf(-(xr + hr)));
            float zv = 1.f / (1.f + expf(-(xz + hz)));
            float nv = tanhf(xn + rv * hn);
            float hp = h_s[cur][jg][r];
            float hnw = (1.f - zv) * nv + zv * hp;
            h_s[nb][jg][r] = hnw;
            sts_cluster_f32(smem_u32(&h_s[nb][jg][r]), peer, hnw);
            rec[(size_t)m * (2 * Hh) + dir * Hh + jg] = hnw;
        }

        // release our DSMEM writes / acquire peer's before next phase 1
        CLUSTER_SYNC();
        cur = nb;
    }

    if (merged) {
        for (int idx = tid; idx < 1024; idx += 384) {
            const int r  = idx >> 7;
            const int jj = idx & 127;
            const int jg = (int)rank * 128 + jj;
            merged[(b0 + r) * (2 * Hh) + dir * Hh + jg] = h_s[cur][jg][r];
        }
    }
}

// ============================================================================
// Attention + output. One CTA per batch row, 256 threads. (unchanged)
// ============================================================================
__global__ void __launch_bounds__(256)
attn_kernel(const float* __restrict__ rec2, const float* __restrict__ merged,
            float* __restrict__ out) {
    const int b   = blockIdx.x;
    const int tid = threadIdx.x;
    __shared__ __align__(16) float mg[512];
    __shared__ float sc[256];
    __shared__ float red[256];

    mg[tid]       = merged[b * 512 + tid];
    mg[tid + 256] = merged[b * 512 + 256 + tid];
    __syncthreads();

    const float* base = rec2 + (size_t)b * Tn * 512;
    const float4* row = (const float4*)(base + (size_t)tid * 512);
    const float4* m4  = (const float4*)mg;
    float s = 0.f;
#pragma unroll 8
    for (int i = 0; i < 128; i++) {
        float4 a = row[i], c = m4[i];
        s += a.x * c.x + a.y * c.y + a.z * c.z + a.w * c.w;
    }
    sc[tid]  = s;
    red[tid] = s;
    __syncthreads();
    for (int off = 128; off; off >>= 1) {
        if (tid < off) red[tid] = fmaxf(red[tid], red[tid + off]);
        __syncthreads();
    }
    const float mx = red[0];
    __syncthreads();
    const float e = expf(s - mx);
    red[tid] = e;
    sc[tid]  = e;
    __syncthreads();
    for (int off = 128; off; off >>= 1) {
        if (tid < off) red[tid] += red[tid + off];
        __syncthreads();
    }
    const float inv = 1.f / red[0];
    __syncthreads();

    float acc0 = 0.f, acc1 = 0.f;
    for (int t = 0; t < Tn; t++) {
        const float w = sc[t] * inv;
        acc0 += base[(size_t)t * 512 + tid] * w;
        acc1 += base[(size_t)t * 512 + 256 + tid] * w;
    }
    float* ob = out + (size_t)b * 1024;
    ob[tid]       = acc0;
    ob[256 + tid] = acc1;
    ob[512 + tid] = base[(size_t)255 * 512 + tid];
    ob[768 + tid] = base[(size_t)255 * 512 + 256 + tid];
}

// ============================================================================
extern "C" void kernel_launch(void* const* d_in, const int* in_sizes, int n_in,
                              void* d_out, int out_size) {
    const float* input = (const float*)d_in[0];
    const float* wih1f = (const float*)d_in[1];
    const float* whh1f = (const float*)d_in[2];
    const float* bih1f = (const float*)d_in[3];
    const float* bhh1f = (const float*)d_in[4];
    const float* wih1r = (const float*)d_in[5];
    const float* whh1r = (const float*)d_in[6];
    const float* bih1r = (const float*)d_in[7];
    const float* bhh1r = (const float*)d_in[8];
    const float* wih2f = (const float*)d_in[9];
    const float* whh2f = (const float*)d_in[10];
    const float* bih2f = (const float*)d_in[11];
    const float* bhh2f = (const float*)d_in[12];
    const float* wih2r = (const float*)d_in[13];
    const float* whh2r = (const float*)d_in[14];
    const float* bih2r = (const float*)d_in[15];
    const float* bhh2r = (const float*)d_in[16];

    float *xg, *rec1, *rec2, *merged, *wpk;
    cudaGetSymbolAddress((void**)&xg, g_xg);
    cudaGetSymbolAddress((void**)&rec1, g_rec1);
    cudaGetSymbolAddress((void**)&rec2, g_rec2);
    cudaGetSymbolAddress((void**)&merged, g_merged);
    cudaGetSymbolAddress((void**)&wpk, g_wpk);

    // Interleave all 4 recurrent weight matrices (cluster-split layout)
    prep_weights<<<(4 * G3 * Hh + 255) / 256, 256>>>(whh1f, whh1r, whh2f, whh2r);

    // Layer 1
    igemm_kernel<NIN><<<dim3(12, 512), 256>>>(input, wih1f, wih1r, bih1f, bih1r, xg);
    scan_kernel<<<128, 384>>>(xg, wpk + 0 * (G3 * Hh), wpk + 1 * (G3 * Hh),
                              bhh1f, bhh1r, rec1, nullptr);
    // Layer 2
    igemm_kernel<512><<<dim3(12, 512), 256>>>(rec1, wih2f, wih2r, bih2f, bih2r, xg);
    scan_kernel<<<128, 384>>>(xg, wpk + 2 * (G3 * Hh), wpk + 3 * (G3 * Hh),
                              bhh2f, bhh2r, rec2, merged);
    // Attention + output
    attn_kernel<<<256, 256>>>(rec2, merged, (float*)d_out);
}